// round 6
// baseline (speedup 1.0000x reference)
#include <cuda_runtime.h>
#include <cstdint>

#define STATE_DIM 512
#define AFEAT 64
#define HID 256
#define HID2 128
#define KACT 1000
#define NROWS 256000
#define TILE_M 64
#define NTILES 4000            // 256000 / 64

__device__ float g_hstate[256 * HID];
__device__ __align__(16) float g_w1af[16384];   // W1a frag-ordered, 64 KB

__device__ __forceinline__ uint32_t f2tf(float f) {
    uint32_t r;
    asm("cvt.rna.tf32.f32 %0, %1;" : "=r"(r) : "f"(f));
    return r;
}

// m16n8k8 tf32 MMA, C += A*B (row.col)
__device__ __forceinline__ void mma8(float* c, const uint4& a, uint32_t b0, uint32_t b1) {
    asm volatile("mma.sync.aligned.m16n8k8.row.col.f32.tf32.tf32.f32 "
        "{%0,%1,%2,%3}, {%4,%5,%6,%7}, {%8,%9}, {%0,%1,%2,%3};"
        : "+f"(c[0]), "+f"(c[1]), "+f"(c[2]), "+f"(c[3])
        : "r"(a.x), "r"(a.y), "r"(a.z), "r"(a.w), "r"(b0), "r"(b1));
}

// ---------------------------------------------------------------------------
// Fused prep: blocks [0,64) compute h_state (exact fp32); blocks [64,128)
// build W1a fragments (tf32) into g_w1af.
// ---------------------------------------------------------------------------
__global__ __launch_bounds__(256) void prep_kernel(
    const float* __restrict__ state,
    const float* __restrict__ W1,
    const float* __restrict__ b1)
{
    const int t = threadIdx.x;
    if (blockIdx.x >= 64) {
        // W1a -> frag order: [ng(4)][ks(8)][np(4)][lane(32)] float4
        // float4 = (nt0.b0, nt0.b1, nt1.b0, nt1.b1)
        int idx = (blockIdx.x - 64) * 256 + t;             // 0..16383
        int ri = idx & 3, lane = (idx >> 2) & 31;
        int np = (idx >> 7) & 3, ks = (idx >> 9) & 7, ng = (idx >> 12) & 3;
        int col  = ng * 64 + np * 16 + ((ri & 2) ? 8 : 0) + (lane >> 2);
        int krow = ks * 8 + (lane & 3) + ((ri & 1) ? 4 : 0);
        ((uint32_t*)g_w1af)[idx] = f2tf(W1[(STATE_DIM + krow) * HID + col]);
        return;
    }
    __shared__ float s[4 * STATE_DIM];
    const int b0 = blockIdx.x * 4;
    for (int i = t; i < 4 * STATE_DIM; i += 256)
        s[i] = state[b0 * STATE_DIM + i];
    __syncthreads();

    float a0, a1, a2, a3;
    a0 = a1 = a2 = a3 = b1[t];
#pragma unroll 8
    for (int k = 0; k < STATE_DIM; k++) {
        float w = W1[k * HID + t];
        a0 = fmaf(s[k], w, a0);
        a1 = fmaf(s[512 + k], w, a1);
        a2 = fmaf(s[1024 + k], w, a2);
        a3 = fmaf(s[1536 + k], w, a3);
    }
    g_hstate[(b0 + 0) * HID + t] = a0;
    g_hstate[(b0 + 1) * HID + t] = a1;
    g_hstate[(b0 + 2) * HID + t] = a2;
    g_hstate[(b0 + 3) * HID + t] = a3;
}

// ---------------------------------------------------------------------------
// Main fused MLP. 512 threads = 16 warps in 4(M)x4(N) grid, TILE_M=64.
// SMEM (floats):
//   sW2f 32768 | sH1f 16384 | sAf 4096 | sHS 1024 | sB2 128 | sW3 128 | sOut 64
// ---------------------------------------------------------------------------
#define OFF_W2F 0
#define OFF_H1F 32768
#define OFF_AF  49152
#define OFF_HS  53248
#define OFF_B2  54272
#define OFF_W3  54400
#define OFF_OUT 54528
#define SMEM_FLOATS 54600
#define SMEM_BYTES (SMEM_FLOATS * 4)

__global__ void __launch_bounds__(512, 1) actor_main(
    const float* __restrict__ af, const float* __restrict__ W2,
    const float* __restrict__ b2, const float* __restrict__ W3,
    const float* __restrict__ b3, float* __restrict__ out)
{
    extern __shared__ float sm[];
    float* sW2f = sm + OFF_W2F;
    float* sH1f = sm + OFF_H1F;
    float* sAf  = sm + OFF_AF;
    float* sHS  = sm + OFF_HS;     // [2][512]
    float* sB2  = sm + OFF_B2;
    float* sW3  = sm + OFF_W3;
    float* sOut = sm + OFF_OUT;

    const int t = threadIdx.x;
    const int lane = t & 31;
    const int w = t >> 5;
    const int mg = w & 3;          // rows mg*16 .. +15
    const int ng = w >> 2;         // L1: cols ng*64..; L2: cols ng*32..

    // ---- build W2 frags in SMEM: [ng(4)][ks2(32)][np(2)][lane(32)] float4 ----
    for (int i = t; i < 32768; i += 512) {
        int ri = i & 3, ln = (i >> 2) & 31;
        int np = (i >> 7) & 1, ks = (i >> 8) & 31, g = (i >> 13) & 3;
        int col  = g * 32 + np * 16 + ((ri & 2) ? 8 : 0) + (ln >> 2);
        int krow = ks * 8 + (ln & 3) + ((ri & 1) ? 4 : 0);
        ((uint32_t*)sW2f)[i] = f2tf(W2[krow * HID2 + col]);
    }
    if (t < 128) { sB2[t] = b2[t]; sW3[t] = W3[t]; }
    if (t < 64) sOut[t] = 0.f;

    // ---- stage helpers ----
    // A-fragment convention (m16n8k8): reg bit0 = row+8, reg bit1 = k+4
    auto scatter_af = [&](const float4* pf) {
#pragma unroll
        for (int j = 0; j < 2; j++) {
            int fi = (j * 512 + t) * 4;
            const float4 v = pf[j];
#pragma unroll
            for (int e = 0; e < 4; e++) {
                int row = (fi + e) >> 6, feat = (fi + e) & 63;
                int ks = feat >> 3, c = feat & 7;
                int ln = ((row & 7) << 2) | (c & 3);
                int rg = ((row >> 3) & 1) + 2 * (c >> 2);
                float val = (e == 0) ? v.x : (e == 1) ? v.y : (e == 2) ? v.z : v.w;
                ((uint32_t*)sAf)[((((row >> 4) * 8 + ks) * 32 + ln) << 2) + rg] = f2tf(val);
            }
        }
    };
    auto stage_hs = [&](int tl, int buf) {
        int r0 = tl * TILE_M;
        int blo = r0 / KACT;
        int bhi = (r0 + TILE_M - 1) / KACT;
        sHS[buf * 512 + t] = g_hstate[(t < 256 ? blo : bhi) * HID + (t & 255)];
    };

    // ---- prologue: stage first tile ----
    int tile = blockIdx.x;
    {
        float4 pf[2];
        const float4* src = (const float4*)af + (size_t)tile * (TILE_M * AFEAT / 4);
#pragma unroll
        for (int j = 0; j < 2; j++) pf[j] = src[j * 512 + t];
        scatter_af(pf);
        stage_hs(tile, 0);
    }
    __syncthreads();

    const float bias3 = __ldg(b3);
    const uint4* w1v = (const uint4*)g_w1af;
    const uint4* w2v = (const uint4*)sW2f;
    const uint4* afv = (const uint4*)sAf;
    const uint4* h1v = (const uint4*)sH1f;

    int it = 0;
    for (; tile < NTILES; tile += gridDim.x, it++) {
        const int row0 = tile * TILE_M;
        const int ntile = tile + gridDim.x;
        const int cur = it & 1, nxt = cur ^ 1;
        const int split = (row0 / KACT + 1) * KACT - row0;   // rows >= split -> next batch

        // ---- prefetch next tile's af ----
        float4 pf[2];
        if (ntile < NTILES) {
            const float4* src = (const float4*)af + (size_t)ntile * (TILE_M * AFEAT / 4);
#pragma unroll
            for (int j = 0; j < 2; j++) pf[j] = src[j * 512 + t];
        }

        // ---- L1: C = af @ W1a, init C = h_state (exact fp32) ----
        // C-fragment convention (m16n8): reg bit0 = col parity, reg bit1 = row+8
        float acc[8][4];
        const float* hsc = sHS + cur * 512;
        {
            const int r = mg * 16 + (lane >> 2);
#pragma unroll
            for (int nt = 0; nt < 8; nt++)
#pragma unroll
            for (int rg = 0; rg < 4; rg++) {
                int rr = r + (rg >> 1) * 8;
                int c = ng * 64 + nt * 8 + 2 * (lane & 3) + (rg & 1);
                acc[nt][rg] = hsc[(rr >= split ? 256 : 0) + c];
            }
        }
#pragma unroll
        for (int ks = 0; ks < 8; ks++) {
            uint4 a = afv[(mg * 8 + ks) * 32 + lane];
#pragma unroll
            for (int np = 0; np < 4; np++) {
                uint4 b = w1v[((ng * 8 + ks) * 4 + np) * 32 + lane];
                mma8(acc[np * 2],     a, b.x, b.y);
                mma8(acc[np * 2 + 1], a, b.z, b.w);
            }
        }
        // ---- ep1: relu -> tf32 -> sH1f in L2-A-frag order ----
#pragma unroll
        for (int nt = 0; nt < 8; nt++)
#pragma unroll
        for (int rg = 0; rg < 4; rg++) {
            int ks2 = ng * 8 + nt;                       // k (=h1 col) / 8
            int cc  = 2 * (lane & 3) + (rg & 1);         // k within 8-slice
            int ln  = ((lane >> 2) << 2) | (cc & 3);     // (row&7)<<2 | (k&3)
            int rg2 = (rg >> 1) + 2 * (cc >> 2);         // A-conv: bit0=row+8, bit1=k+4
            float v = fmaxf(acc[nt][rg], 0.f);
            ((uint32_t*)sH1f)[(((mg * 32 + ks2) * 32 + ln) << 2) + rg2] = f2tf(v);
        }
        __syncthreads();   // S1: h1 ready, afrag free

        // ---- stage next tile while L2 runs ----
        if (ntile < NTILES) {
            scatter_af(pf);
            stage_hs(ntile, nxt);
        }

        // ---- L2: C2 = h1 @ W2 ----
        float acc2[4][4];
#pragma unroll
        for (int nt = 0; nt < 4; nt++)
#pragma unroll
        for (int rg = 0; rg < 4; rg++) acc2[nt][rg] = 0.f;
#pragma unroll 8
        for (int ks = 0; ks < 32; ks++) {
            uint4 a = h1v[(mg * 32 + ks) * 32 + lane];
#pragma unroll
            for (int np = 0; np < 2; np++) {
                uint4 b = w2v[((ng * 32 + ks) * 2 + np) * 32 + lane];
                mma8(acc2[np * 2],     a, b.x, b.y);
                mma8(acc2[np * 2 + 1], a, b.z, b.w);
            }
        }

        // ---- L3: out = relu(C2 + b2) . W3 + b3 ----
        float part[2] = {0.f, 0.f};
#pragma unroll
        for (int nt = 0; nt < 4; nt++)
#pragma unroll
        for (int rg = 0; rg < 4; rg++) {
            int c = ng * 32 + nt * 8 + 2 * (lane & 3) + (rg & 1);
            float v = fmaxf(acc2[nt][rg] + sB2[c], 0.f);
            part[rg >> 1] += v * sW3[c];                 // rg>>1 = row-offset bit
        }
#pragma unroll
        for (int rb = 0; rb < 2; rb++) {
            float v = part[rb];
            v += __shfl_xor_sync(0xffffffffu, v, 1);
            v += __shfl_xor_sync(0xffffffffu, v, 2);
            if ((lane & 3) == 0)
                atomicAdd(&sOut[mg * 16 + rb * 8 + (lane >> 2)], v);
        }
        __syncthreads();   // S2: outstage complete, h1 reads done
        if (t < 64) {
            out[row0 + t] = sOut[t] + bias3;
            sOut[t] = 0.f;
        }
        __syncthreads();   // S3: outstage rezeroed, buffers free
    }
}

// ---------------------------------------------------------------------------
extern "C" void kernel_launch(void* const* d_in, const int* in_sizes, int n_in,
                              void* d_out, int out_size)
{
    const float* state = (const float*)d_in[0];
    const float* afeats = (const float*)d_in[1];
    const float* W1    = (const float*)d_in[2];
    const float* b1    = (const float*)d_in[3];
    const float* W2    = (const float*)d_in[4];
    const float* b2    = (const float*)d_in[5];
    const float* W3    = (const float*)d_in[6];
    const float* b3    = (const float*)d_in[7];
    float* out = (float*)d_out;
    (void)in_sizes; (void)n_in; (void)out_size;

    static int sm_count = 0;
    if (sm_count == 0) {
        cudaDeviceGetAttribute(&sm_count, cudaDevAttrMultiProcessorCount, 0);
        if (sm_count <= 0) sm_count = 148;
        cudaFuncSetAttribute(actor_main,
                             cudaFuncAttributeMaxDynamicSharedMemorySize, SMEM_BYTES);
    }

    prep_kernel<<<128, 256>>>(state, W1, b1);
    actor_main<<<sm_count, 512, SMEM_BYTES>>>(afeats, W2, b2, W3, b3, out);
}

// round 7
// speedup vs baseline: 1.6233x; 1.6233x over previous
#include <cuda_runtime.h>
#include <cuda_fp16.h>
#include <cstdint>

#define STATE_DIM 512
#define AFEAT 64
#define HID 256
#define HID2 128
#define KACT 1000
#define NROWS 256000
#define TILE_M 64
#define NTILES 4000            // 256000 / 64

__device__ float g_hstate[256 * HID];

__device__ __forceinline__ uint32_t pk(float lo, float hi) {
    __half2 h = __floats2half2_rn(lo, hi);      // low 16 bits = lo
    return *(uint32_t*)&h;
}
__device__ __forceinline__ uint32_t pkr(float lo, float hi) {
    return pk(fmaxf(lo, 0.f), fmaxf(hi, 0.f));
}

// m16n8k16 f16 MMA, f32 accum, C += A*B (row.col)
__device__ __forceinline__ void mma16(float* c, const uint4& a, uint32_t b0, uint32_t b1) {
    asm volatile("mma.sync.aligned.m16n8k16.row.col.f32.f16.f16.f32 "
        "{%0,%1,%2,%3}, {%4,%5,%6,%7}, {%8,%9}, {%0,%1,%2,%3};"
        : "+f"(c[0]), "+f"(c[1]), "+f"(c[2]), "+f"(c[3])
        : "r"(a.x), "r"(a.y), "r"(a.z), "r"(a.w), "r"(b0), "r"(b1));
}

// ---------------------------------------------------------------------------
// hstate: h_state[b][j] = state[b] . W1[:512,j] + b1[j]   (exact fp32)
// ---------------------------------------------------------------------------
__global__ __launch_bounds__(256) void hstate_kernel(
    const float* __restrict__ state,
    const float* __restrict__ W1,
    const float* __restrict__ b1)
{
    __shared__ float s[4 * STATE_DIM];
    const int b0 = blockIdx.x * 4;
    const int t = threadIdx.x;
    for (int i = t; i < 4 * STATE_DIM; i += 256)
        s[i] = state[b0 * STATE_DIM + i];
    __syncthreads();

    float a0, a1, a2, a3;
    a0 = a1 = a2 = a3 = b1[t];
#pragma unroll 8
    for (int k = 0; k < STATE_DIM; k++) {
        float w = W1[k * HID + t];
        a0 = fmaf(s[k], w, a0);
        a1 = fmaf(s[512 + k], w, a1);
        a2 = fmaf(s[1024 + k], w, a2);
        a3 = fmaf(s[1536 + k], w, a3);
    }
    g_hstate[(b0 + 0) * HID + t] = a0;
    g_hstate[(b0 + 1) * HID + t] = a1;
    g_hstate[(b0 + 2) * HID + t] = a2;
    g_hstate[(b0 + 3) * HID + t] = a3;
}

// ---------------------------------------------------------------------------
// Main fused MLP. 512 threads = 16 warps in 4(M)x4(N) grid, TILE_M=64, fp16.
//
// B-frag uint4 convention (n8 pair at col base): x=(n8=0,k0..7) y=(n8=0,k8..15)
//                                                z=(n8=1,k0..7) w=(n8=1,k8..15)
// A-frag uint4: x=(r,k0..) y=(r+8,k0..) z=(r,k8..) w=(r+8,k8..), f16x2 lo=even k
//
// SMEM (float units):
//  sW2f 16384 | sW1f 8192 | sH1f 8192 | sAf 2048 | sHS 1024 | sB2 128 | sW3 128 | sOut 64
// ---------------------------------------------------------------------------
#define OFF_W2F 0
#define OFF_W1F 16384
#define OFF_H1F 24576
#define OFF_AF  32768
#define OFF_HS  34816
#define OFF_B2  35840
#define OFF_W3  35968
#define OFF_OUT 36096
#define SMEM_FLOATS 36160
#define SMEM_BYTES (SMEM_FLOATS * 4)

__global__ void __launch_bounds__(512, 1) actor_main(
    const float* __restrict__ af, const float* __restrict__ W1,
    const float* __restrict__ W2, const float* __restrict__ b2,
    const float* __restrict__ W3, const float* __restrict__ b3,
    float* __restrict__ out)
{
    extern __shared__ float sm[];
    uint32_t* sW2f = (uint32_t*)(sm + OFF_W2F);
    uint32_t* sW1f = (uint32_t*)(sm + OFF_W1F);
    uint32_t* sH1f = (uint32_t*)(sm + OFF_H1F);
    uint32_t* sAf  = (uint32_t*)(sm + OFF_AF);
    float* sHS  = sm + OFF_HS;     // [2][512]
    float* sB2  = sm + OFF_B2;
    float* sW3  = sm + OFF_W3;
    float* sOut = sm + OFF_OUT;

    const int t = threadIdx.x;
    const int lane = t & 31;
    const int w = t >> 5;
    const int mg = w & 3;          // rows mg*16 .. +15
    const int ng = w >> 2;         // L1: cols ng*64..; L2: cols ng*32..

    // ---- build W2 frags: [ng(4)][ks(16)][np(2)][lane(32)] uint4 ----
    for (int i = t; i < 16384; i += 512) {
        int ws = i & 3, ln = (i >> 2) & 31;
        int np = (i >> 7) & 1, ks = (i >> 8) & 15, g = (i >> 12) & 3;
        int krow = ks * 16 + (ws & 1) * 8 + (ln & 3) * 2;
        int col  = g * 32 + np * 16 + (ws >> 1) * 8 + (ln >> 2);
        sW2f[i] = pk(W2[krow * HID2 + col], W2[(krow + 1) * HID2 + col]);
    }
    // ---- build W1a frags: [ng(4)][ks(4)][np(4)][lane(32)] uint4 ----
    for (int i = t; i < 8192; i += 512) {
        int ws = i & 3, ln = (i >> 2) & 31;
        int np = (i >> 7) & 3, ks = (i >> 9) & 3, g = (i >> 11) & 3;
        int krow = STATE_DIM + ks * 16 + (ws & 1) * 8 + (ln & 3) * 2;
        int col  = g * 64 + np * 16 + (ws >> 1) * 8 + (ln >> 2);
        sW1f[i] = pk(W1[krow * HID + col], W1[(krow + 1) * HID + col]);
    }
    if (t < 128) { sB2[t] = b2[t]; sW3[t] = W3[t]; }
    if (t < 64) sOut[t] = 0.f;

    // ---- af staging: thread t builds one A-frag uint4 per tile ----
    const int srg4 = t >> 7;            // row group (16 rows)
    const int sks  = (t >> 5) & 3;      // k16 group
    const int sl   = t & 31;
    const int srow = srg4 * 16 + (sl >> 2);
    const int scol = sks * 16 + (sl & 3) * 2;

    auto load_af = [&](int tl, float2* p) {
        const float* base = af + (size_t)(tl * TILE_M + srow) * AFEAT + scol;
        p[0] = *(const float2*)(base);
        p[1] = *(const float2*)(base + 8);
        p[2] = *(const float2*)(base + 8 * AFEAT);
        p[3] = *(const float2*)(base + 8 * AFEAT + 8);
    };
    auto store_af = [&](const float2* p) {
        uint4 v;
        v.x = pk(p[0].x, p[0].y);   // (r,   k0)
        v.y = pk(p[2].x, p[2].y);   // (r+8, k0)
        v.z = pk(p[1].x, p[1].y);   // (r,   k0+8)
        v.w = pk(p[3].x, p[3].y);   // (r+8, k0+8)
        ((uint4*)sAf)[(srg4 * 4 + sks) * 32 + sl] = v;
    };
    auto stage_hs = [&](int tl, int buf) {
        int r0 = tl * TILE_M;
        int blo = r0 / KACT;
        int bhi = (r0 + TILE_M - 1) / KACT;
        sHS[buf * 512 + t] = g_hstate[(t < 256 ? blo : bhi) * HID + (t & 255)];
    };

    // ---- prologue ----
    int tile = blockIdx.x;
    {
        float2 p[4];
        load_af(tile, p);
        store_af(p);
        stage_hs(tile, 0);
    }
    __syncthreads();

    const float bias3 = __ldg(b3);
    const uint4* w1v = (const uint4*)sW1f;
    const uint4* w2v = (const uint4*)sW2f;
    const uint4* afv = (const uint4*)sAf;
    const uint4* h1v = (const uint4*)sH1f;

    int it = 0;
    for (; tile < NTILES; tile += gridDim.x, it++) {
        const int row0 = tile * TILE_M;
        const int ntile = tile + gridDim.x;
        const int cur = it & 1, nxt = cur ^ 1;
        const int split = (row0 / KACT + 1) * KACT - row0;

        // ---- prefetch next tile's af (DRAM latency overlaps L1 GEMM) ----
        float2 p[4];
        if (ntile < NTILES) load_af(ntile, p);

        // ---- L1: C = af @ W1a, init C = h_state (exact fp32) ----
        // C-frag: bit0 = col parity, bit1 = row+8
        float acc[8][4];
        const float* hsc = sHS + cur * 512;
        {
            const int r = mg * 16 + (lane >> 2);
#pragma unroll
            for (int nt = 0; nt < 8; nt++)
#pragma unroll
            for (int rg = 0; rg < 4; rg++) {
                int rr = r + (rg >> 1) * 8;
                int c = ng * 64 + nt * 8 + 2 * (lane & 3) + (rg & 1);
                acc[nt][rg] = hsc[(rr >= split ? 256 : 0) + c];
            }
        }
#pragma unroll
        for (int ks = 0; ks < 4; ks++) {
            uint4 a = afv[(mg * 4 + ks) * 32 + lane];
#pragma unroll
            for (int np = 0; np < 4; np++) {
                uint4 b = w1v[((ng * 4 + ks) * 4 + np) * 32 + lane];
                mma16(acc[np * 2],     a, b.x, b.y);
                mma16(acc[np * 2 + 1], a, b.z, b.w);
            }
        }
        // ---- ep1: relu -> f16 pairs -> sH1f as L2 A-frags (4x STS.128) ----
        // k-pair = C col-pair (same lane), A-reg bit1 = nt parity, bit0 = row+8
#pragma unroll
        for (int q = 0; q < 4; q++) {
            uint4 v;
            v.x = pkr(acc[2 * q][0],     acc[2 * q][1]);
            v.y = pkr(acc[2 * q][2],     acc[2 * q][3]);
            v.z = pkr(acc[2 * q + 1][0], acc[2 * q + 1][1]);
            v.w = pkr(acc[2 * q + 1][2], acc[2 * q + 1][3]);
            ((uint4*)sH1f)[(mg * 16 + ng * 4 + q) * 32 + lane] = v;
        }
        __syncthreads();   // S1: h1 ready, sAf free

        // ---- stage next tile while L2 runs ----
        if (ntile < NTILES) {
            store_af(p);
            stage_hs(ntile, nxt);
        }

        // ---- L2: C2 = h1 @ W2 ----
        float acc2[4][4];
#pragma unroll
        for (int nt = 0; nt < 4; nt++)
#pragma unroll
        for (int rg = 0; rg < 4; rg++) acc2[nt][rg] = 0.f;
#pragma unroll
        for (int ks = 0; ks < 16; ks++) {
            uint4 a = h1v[(mg * 16 + ks) * 32 + lane];
#pragma unroll
            for (int np = 0; np < 2; np++) {
                uint4 b = w2v[((ng * 16 + ks) * 2 + np) * 32 + lane];
                mma16(acc2[np * 2],     a, b.x, b.y);
                mma16(acc2[np * 2 + 1], a, b.z, b.w);
            }
        }

        // ---- L3: out = relu(C2 + b2) . W3 + b3 ----
        float part[2] = {0.f, 0.f};
#pragma unroll
        for (int nt = 0; nt < 4; nt++)
#pragma unroll
        for (int rg = 0; rg < 4; rg++) {
            int c = ng * 32 + nt * 8 + 2 * (lane & 3) + (rg & 1);
            float v = fmaxf(acc2[nt][rg] + sB2[c], 0.f);
            part[rg >> 1] += v * sW3[c];
        }
#pragma unroll
        for (int rb = 0; rb < 2; rb++) {
            float v = part[rb];
            v += __shfl_xor_sync(0xffffffffu, v, 1);
            v += __shfl_xor_sync(0xffffffffu, v, 2);
            if ((lane & 3) == 0)
                atomicAdd(&sOut[mg * 16 + rb * 8 + (lane >> 2)], v);
        }
        __syncthreads();   // S2: L3 atomics done, h1 reads done
        if (t < 64) {
            out[row0 + t] = sOut[t] + bias3;
            sOut[t] = 0.f;
        }
        __syncthreads();   // S3: buffers free
    }
}

// ---------------------------------------------------------------------------
extern "C" void kernel_launch(void* const* d_in, const int* in_sizes, int n_in,
                              void* d_out, int out_size)
{
    const float* state = (const float*)d_in[0];
    const float* afeats = (const float*)d_in[1];
    const float* W1    = (const float*)d_in[2];
    const float* b1    = (const float*)d_in[3];
    const float* W2    = (const float*)d_in[4];
    const float* b2    = (const float*)d_in[5];
    const float* W3    = (const float*)d_in[6];
    const float* b3    = (const float*)d_in[7];
    float* out = (float*)d_out;
    (void)in_sizes; (void)n_in; (void)out_size;

    static int sm_count = 0;
    if (sm_count == 0) {
        cudaDeviceGetAttribute(&sm_count, cudaDevAttrMultiProcessorCount, 0);
        if (sm_count <= 0) sm_count = 148;
        cudaFuncSetAttribute(actor_main,
                             cudaFuncAttributeMaxDynamicSharedMemorySize, SMEM_BYTES);
    }

    hstate_kernel<<<64, 256>>>(state, W1, b1);
    actor_main<<<sm_count, 512, SMEM_BYTES>>>(afeats, W1, W2, b2, W3, b3, out);
}